// round 1
// baseline (speedup 1.0000x reference)
#include <cuda_runtime.h>

#define HW 128
#define CC 64
#define BBATCH 32
#define KK 1000
#define LL 12
#define OO 24

// Intermediate activation h in NHWC layout: [B][H][W][C]  (128 MB scratch)
__device__ float g_h[BBATCH * HW * HW * CC];

// ---------- packed f32x2 helpers (Blackwell FFMA2) ----------
__device__ __forceinline__ unsigned long long ffma2(unsigned long long a,
                                                    unsigned long long b,
                                                    unsigned long long c) {
    unsigned long long d;
    asm("fma.rn.f32x2 %0, %1, %2, %3;" : "=l"(d) : "l"(a), "l"(b), "l"(c));
    return d;
}
__device__ __forceinline__ unsigned long long pack2(float lo, float hi) {
    unsigned long long d;
    asm("mov.b64 %0, {%1, %2};" : "=l"(d) : "f"(lo), "f"(hi));
    return d;
}
__device__ __forceinline__ void unpack2(unsigned long long v, float& lo, float& hi) {
    asm("mov.b64 {%0, %1}, %2;" : "=f"(lo), "=f"(hi) : "l"(v));
}

// ============================================================================
// Kernel A: 3x3 conv (pad 1) + bias + LeakyReLU(0.02), NCHW in -> NHWC out.
// One block per (row y, image b). 256 threads:
//   tx = t&31  -> 4 pixels (px = tx*4 + i)
//   ty = t>>5  -> 8 output channels (co = ty*8 .. +7), held as 4 f32x2 pairs
// c_in processed in chunks of 8 through shared memory.
// ============================================================================
__global__ __launch_bounds__(256) void conv_lrelu_kernel(
    const float* __restrict__ x,      // [B][C][H][W]
    const float* __restrict__ w,      // [Cout][Cin][3][3]
    const float* __restrict__ bias)   // [Cout]
{
    // xs: 8 ci x 3 dy x 136 (4-word left pad so float4 reads stay 16B aligned;
    //     data at [4..131], zero pads at [3] and [132])
    __shared__ float xs[8 * 3 * 136];          // 13,056 B
    // ws: [rem=ci*9+dy*3+dx (72)][co (64)] with stride 66 to dodge store conflicts;
    //     adjacent co pairs read as float2 (broadcast across the warp).
    __shared__ float ws[72 * 66];              // 19,008 B

    const int y = blockIdx.x;
    const int b = blockIdx.y;
    const int t = threadIdx.x;
    const int tx = t & 31;
    const int ty = t >> 5;

    unsigned long long acc2[4][4];
#pragma unroll
    for (int cp = 0; cp < 4; cp++)
#pragma unroll
        for (int i = 0; i < 4; i++) acc2[cp][i] = 0ULL;

    for (int chunk = 0; chunk < 8; ++chunk) {
        const int ci0 = chunk * 8;

        // ---- stage input rows (y-1, y, y+1) for 8 input channels ----
        for (int i = t; i < 8 * 3 * 128; i += 256) {
            int ci = i / 384;
            int r  = i - ci * 384;
            int dy = r >> 7;
            int px = r & 127;
            int row = y + dy - 1;
            float v = 0.f;
            if ((unsigned)row < 128u)
                v = x[(((b * CC + ci0 + ci) * HW + row) << 7) + px];
            xs[(ci * 3 + dy) * 136 + 4 + px] = v;
        }
        if (t < 48) {  // zero the horizontal halo pads
            int ci = t / 6; int r = t - ci * 6; int dy = r >> 1; int side = r & 1;
            xs[(ci * 3 + dy) * 136 + (side ? 132 : 3)] = 0.f;
        }

        // ---- stage weights for this ci chunk: 64 co x 8 ci x 9 taps ----
        for (int i = t; i < 4608; i += 256) {
            int co  = i / 72;
            int rem = i - co * 72;             // rem = ci*9 + dy*3 + dx
            ws[rem * 66 + co] = w[co * 576 + ci0 * 9 + rem];
        }
        __syncthreads();

        // ---- main FMA loop ----
#pragma unroll
        for (int ci = 0; ci < 8; ++ci) {
#pragma unroll
            for (int dy = 0; dy < 3; ++dy) {
                const float* xr = &xs[(ci * 3 + dy) * 136];
                float4 V = *reinterpret_cast<const float4*>(xr + 4 + tx * 4);
                float v0 = xr[3 + tx * 4];
                float v5 = xr[8 + tx * 4];
                unsigned long long bb[6];
                bb[0] = pack2(v0, v0);  bb[1] = pack2(V.x, V.x);
                bb[2] = pack2(V.y, V.y); bb[3] = pack2(V.z, V.z);
                bb[4] = pack2(V.w, V.w); bb[5] = pack2(v5, v5);
#pragma unroll
                for (int dx = 0; dx < 3; ++dx) {
                    const float2* wrow =
                        reinterpret_cast<const float2*>(&ws[(ci * 9 + dy * 3 + dx) * 66]);
#pragma unroll
                    for (int cp = 0; cp < 4; ++cp) {
                        float2 wp = wrow[ty * 4 + cp];
                        unsigned long long wpp = pack2(wp.x, wp.y);
#pragma unroll
                        for (int i = 0; i < 4; i++)
                            acc2[cp][i] = ffma2(wpp, bb[dx + i], acc2[cp][i]);
                    }
                }
            }
        }
        __syncthreads();
    }

    // ---- epilogue: bias + leaky relu, store NHWC ----
    float* hb = &g_h[((b * HW + y) * HW) * CC];
#pragma unroll
    for (int cp = 0; cp < 4; ++cp) {
        int co = ty * 8 + cp * 2;
        float b0 = bias[co], b1 = bias[co + 1];
#pragma unroll
        for (int i = 0; i < 4; i++) {
            float a0, a1;
            unpack2(acc2[cp][i], a0, a1);
            a0 += b0; a1 += b1;
            a0 = a0 > 0.f ? a0 : 0.02f * a0;
            a1 = a1 > 0.f ? a1 : 0.02f * a1;
            int px = tx * 4 + i;
            *reinterpret_cast<float2*>(&hb[px * CC + co]) = make_float2(a0, a1);
        }
    }
}

// ============================================================================
// Kernel B: gather 12 positions x 64ch from NHWC h, multiply by pred_w^T (24x768).
// One warp per (k,b) pair; pred_w staged through smem in two 36 KB halves.
// out[(k*32+b)*24 + o], matching reference transpose(1,0,2).
// ============================================================================
__global__ __launch_bounds__(256) void gather_fc_kernel(
    const int* __restrict__ pos,     // [K][B][L][2] (x, y)
    const float* __restrict__ pw,    // [24][768]
    const float* __restrict__ pb,    // [24]
    float* __restrict__ out)         // [K][B][24]
{
    __shared__ float wsm[OO * 384];  // 36,864 B: half of pred_w

    const int t = threadIdx.x;
    const int lane = t & 31;
    const int warp = t >> 5;
    const int pair = blockIdx.x * 8 + warp;   // pair = k*32 + b, grid covers exactly 32000
    const int k = pair >> 5;
    const int b = pair & 31;

    float acc[OO];
#pragma unroll
    for (int o = 0; o < OO; o++) acc[o] = 0.f;

    const float* __restrict__ h = g_h;

    for (int half = 0; half < 2; ++half) {
        __syncthreads();
        for (int i = t * 4; i < OO * 384; i += 1024) {
            int o = i / 384;
            int j = i - o * 384;
            *reinterpret_cast<float4*>(&wsm[i]) =
                *reinterpret_cast<const float4*>(&pw[o * 768 + half * 384 + j]);
        }
        __syncthreads();

#pragma unroll
        for (int j24 = 0; j24 < 12; ++j24) {
            int j24g = half * 12 + j24;
            int l = j24g >> 1;
            const int* pp = &pos[((k * BBATCH + b) * LL + l) * 2];
            int px = pp[0];
            int py = pp[1];
            px = px < 0 ? 0 : (px > 127 ? 127 : px);
            py = py < 0 ? 0 : (py > 127 ? 127 : py);
            int c = lane + ((j24g & 1) << 5);
            float hv = h[(((b * HW + py) * HW) + px) * CC + c];
            const float* wc = &wsm[j24 * 32 + lane];
#pragma unroll
            for (int o = 0; o < OO; o++)
                acc[o] += hv * wc[o * 384];
        }
    }

    // warp reduction over the 32 j-lanes
#pragma unroll
    for (int o = 0; o < OO; o++) {
        acc[o] += __shfl_xor_sync(0xffffffffu, acc[o], 16);
        acc[o] += __shfl_xor_sync(0xffffffffu, acc[o], 8);
        acc[o] += __shfl_xor_sync(0xffffffffu, acc[o], 4);
        acc[o] += __shfl_xor_sync(0xffffffffu, acc[o], 2);
        acc[o] += __shfl_xor_sync(0xffffffffu, acc[o], 1);
    }

    if (lane == 0) {
        float* op = &out[pair * OO];
#pragma unroll
        for (int o = 0; o < OO; o++) op[o] = acc[o] + pb[o];
    }
}

// ============================================================================
extern "C" void kernel_launch(void* const* d_in, const int* in_sizes, int n_in,
                              void* d_out, int out_size) {
    const float* x   = (const float*)d_in[0];   // [32][64][128][128]
    const int*   pos = (const int*)  d_in[1];   // [1000][32][12][2]
    const float* cw  = (const float*)d_in[2];   // [64][64][3][3]
    const float* cb  = (const float*)d_in[3];   // [64]
    const float* pw  = (const float*)d_in[4];   // [24][768]
    const float* pb  = (const float*)d_in[5];   // [24]
    float* out = (float*)d_out;                 // [1000][32][24]

    conv_lrelu_kernel<<<dim3(HW, BBATCH), 256>>>(x, cw, cb);
    gather_fc_kernel<<<(KK * BBATCH) / 8, 256>>>(pos, pw, pb, out);
}